// round 4
// baseline (speedup 1.0000x reference)
#include <cuda_runtime.h>
#include <cuda_bf16.h>

#define NUM_SEG 32
#define C 256
#define C4 64   // float4 per row

// Scratch (allocation-free rule: __device__ globals).
// g_sum invariant: ZERO at entry to every kernel_launch. It is zero-initialized
// at module load, and se_mlp_kernel re-zeroes it after consuming it, so the
// invariant is restored by every launch (deterministic, no separate zero pass).
__device__ float  g_sum[NUM_SEG * C];
__device__ float4 g_y4[NUM_SEG * C4];   // gates, float4-aligned

// ---------------------------------------------------------------------------
// Kernel 1: segment sum, single-wave even partition.
// Grid = 152 SMs * 6 CTAs (launch_bounds guarantees 6 resident/SM), each
// block owns a contiguous equal slice of rows -> zero wave quantization and
// zero tail. Walk in 128-row chunks: if idx[chunk_end-1] == cur (sorted =>
// whole chunk is one segment) take the branch-free unrolled path with
// streaming loads; else per-row fallback. Atomic flush only on segment change.
// 256 threads = 64 float4 channel lanes x 4 subrows.
// ---------------------------------------------------------------------------
#define RED_BLOCKS (152 * 6)
#define CHUNK 128

__device__ __forceinline__ void flush_acc(int seg, int c4, float4 a0, float4 a1) {
    float* dst = &g_sum[seg * C + c4 * 4];
    atomicAdd(dst + 0, a0.x + a1.x);
    atomicAdd(dst + 1, a0.y + a1.y);
    atomicAdd(dst + 2, a0.z + a1.z);
    atomicAdd(dst + 3, a0.w + a1.w);
}

__global__ void __launch_bounds__(256, 6)
se_reduce_kernel(const float4* __restrict__ feats,
                 const int*    __restrict__ idx,
                 int N) {
    const int c4  = threadIdx.x & 63;   // channel float4 lane
    const int sub = threadIdx.x >> 6;   // 0..3

    // even contiguous partition of rows across blocks
    long r0 = (long)blockIdx.x * N / gridDim.x;
    long r1 = (long)(blockIdx.x + 1) * N / gridDim.x;
    if (r0 >= r1) return;

    float4 a0 = make_float4(0.f, 0.f, 0.f, 0.f);
    float4 a1 = make_float4(0.f, 0.f, 0.f, 0.f);
    int cur = __ldg(&idx[r0]);

    long cs = r0;
    while (cs < r1) {
        long ce = cs + CHUNK;
        if (ce > r1) ce = r1;
        int s_last = __ldg(&idx[ce - 1]);

        if (s_last == cur) {
            // fast path: whole chunk in this thread's current segment
            const float4* p = feats + (cs + sub) * C4 + c4;
            long r = cs + sub;
            for (; r + 12 < ce; r += 16) {
                float4 v0 = __ldcs(p + 0 * 4 * C4);
                float4 v1 = __ldcs(p + 1 * 4 * C4);
                float4 v2 = __ldcs(p + 2 * 4 * C4);
                float4 v3 = __ldcs(p + 3 * 4 * C4);
                a0.x += v0.x; a0.y += v0.y; a0.z += v0.z; a0.w += v0.w;
                a1.x += v1.x; a1.y += v1.y; a1.z += v1.z; a1.w += v1.w;
                a0.x += v2.x; a0.y += v2.y; a0.z += v2.z; a0.w += v2.w;
                a1.x += v3.x; a1.y += v3.y; a1.z += v3.z; a1.w += v3.w;
                p += 16 * C4;
            }
            for (; r < ce; r += 4) {
                float4 v = __ldcs(p);
                a0.x += v.x; a0.y += v.y; a0.z += v.z; a0.w += v.w;
                p += 4 * C4;
            }
        } else {
            // boundary chunk: per-row segment tracking
            for (long r = cs + sub; r < ce; r += 4) {
                int s = __ldg(&idx[r]);
                float4 v = __ldcs(feats + r * C4 + c4);
                if (s != cur) {
                    flush_acc(cur, c4, a0, a1);
                    a0 = v;
                    a1 = make_float4(0.f, 0.f, 0.f, 0.f);
                    cur = s;
                } else {
                    a0.x += v.x; a0.y += v.y; a0.z += v.z; a0.w += v.w;
                }
            }
        }
        cs = ce;
    }
    flush_acc(cur, c4, a0, a1);
}

// ---------------------------------------------------------------------------
// Kernel 2: one block per segment. Binary-search bounds (sorted idx), mean,
// 256->16 GEMM (16-thread groups + shuffle reduce), ReLU, 16->256 GEMM,
// sigmoid. Afterwards, re-zeroes its g_sum slice (restores the launch
// invariant -> no separate zero kernel needed).
// ---------------------------------------------------------------------------
__global__ void se_mlp_kernel(const int*   __restrict__ idx, int N,
                              const float* __restrict__ W1,
                              const float* __restrict__ b1,
                              const float* __restrict__ W2,
                              const float* __restrict__ b2) {
    const int s = blockIdx.x;
    const int t = threadIdx.x;
    __shared__ float sp[C];
    __shared__ float sh[16];
    __shared__ int   lb[2];

    // lower_bound(idx, s) and lower_bound(idx, s+1)
    if (t < 2) {
        int target = s + t;
        int lo = 0, hi = N;
        while (lo < hi) {
            int mid = (lo + hi) >> 1;
            if (__ldg(&idx[mid]) < target) lo = mid + 1; else hi = mid;
        }
        lb[t] = lo;
    }
    __syncthreads();

    float inv_cnt = 1.0f / fmaxf((float)(lb[1] - lb[0]), 1.0f);
    sp[t] = g_sum[s * C + t] * inv_cnt;
    g_sum[s * C + t] = 0.0f;     // consumer reset: restore zero invariant
    __syncthreads();

    // h[g] = relu(dot(sp, W1[:,g]) + b1[g]); 16 threads per output g
    {
        int g = t >> 4;       // output 0..15
        int l = t & 15;       // lane within group
        float acc = 0.0f;
        #pragma unroll
        for (int k = l; k < C; k += 16) acc += sp[k] * W1[k * 16 + g];
        #pragma unroll
        for (int off = 8; off; off >>= 1)
            acc += __shfl_down_sync(0xffffffffu, acc, off, 16);
        if (l == 0) sh[g] = fmaxf(acc + b1[g], 0.0f);
    }
    __syncthreads();

    // y[t] = sigmoid(dot(sh, W2[:,t]) + b2[t])
    float acc = b2[t];
    #pragma unroll
    for (int k = 0; k < 16; k++) acc += sh[k] * W2[k * C + t];
    ((float*)g_y4)[s * C + t] = 1.0f / (1.0f + __expf(-acc));
}

// ---------------------------------------------------------------------------
// Kernel 3: out = feats * y[batch_idx].  Flat float4 grid-stride with
// streaming loads/stores (feats/out have zero reuse; keep L2 for idx+gates).
// ---------------------------------------------------------------------------
__global__ void se_scale_kernel(const float4* __restrict__ feats,
                                const int*    __restrict__ idx,
                                float4*       __restrict__ out,
                                long total4) {
    long stride = (long)gridDim.x * blockDim.x;
    for (long i = (long)blockIdx.x * blockDim.x + threadIdx.x;
         i < total4; i += stride) {
        int row = (int)(i >> 6);
        int c4  = (int)(i & 63);
        int s   = __ldg(&idx[row]);
        float4 v = __ldcs(feats + i);
        float4 g = g_y4[s * C4 + c4];
        float4 o;
        o.x = v.x * g.x; o.y = v.y * g.y; o.z = v.z * g.z; o.w = v.w * g.w;
        __stcs(out + i, o);
    }
}

// ---------------------------------------------------------------------------
extern "C" void kernel_launch(void* const* d_in, const int* in_sizes, int n_in,
                              void* d_out, int out_size) {
    const float* feats = (const float*)d_in[0];
    const int*   idx   = (const int*)  d_in[1];
    const float* W1    = (const float*)d_in[2];
    const float* b1    = (const float*)d_in[3];
    const float* W2    = (const float*)d_in[4];
    const float* b2    = (const float*)d_in[5];

    const int N = in_sizes[1];               // number of points
    const long total4 = (long)N * C4;

    se_reduce_kernel<<<RED_BLOCKS, 256>>>((const float4*)feats, idx, N);

    se_mlp_kernel<<<NUM_SEG, 256>>>(idx, N, W1, b1, W2, b2);

    se_scale_kernel<<<2432, 256>>>((const float4*)feats, idx,
                                   (float4*)d_out, total4);
}

// round 5
// speedup vs baseline: 1.0087x; 1.0087x over previous
#include <cuda_runtime.h>
#include <cuda_bf16.h>

#define NUM_SEG 32
#define C 256
#define C4 64   // float4 per row

// Scratch (allocation-free rule: __device__ globals).
// g_sum invariant: ZERO at entry to every kernel_launch. Zero-initialized at
// module load; se_mlp_kernel re-zeroes it after consuming it, so the invariant
// is restored by every launch (deterministic, no separate zero pass).
__device__ float  g_sum[NUM_SEG * C];
__device__ float4 g_y4[NUM_SEG * C4];   // gates, float4-aligned

// ---------------------------------------------------------------------------
// Kernel 1: segment sum, single-wave even partition at FULL occupancy.
// Grid = 152 SMs * 8 CTAs, __launch_bounds__(256, 8) => 64 warps/SM (100%),
// 32 regs/thread budget -> slim inner loop (2 in-flight float4 loads,
// 2 accumulators). Each block owns a contiguous equal slice of rows (no wave
// quantization, no tail). Walk in 128-row chunks: if idx[chunk_end-1] == cur
// (sorted => whole chunk one segment) take the branch-free path with
// streaming loads; else per-row fallback. Atomic flush only on segment change.
// 256 threads = 64 float4 channel lanes x 4 subrows.
// ---------------------------------------------------------------------------
#define RED_BLOCKS (152 * 8)
#define CHUNK 128

__device__ __forceinline__ void flush_acc(int seg, int c4, float4 a0, float4 a1) {
    float* dst = &g_sum[seg * C + c4 * 4];
    atomicAdd(dst + 0, a0.x + a1.x);
    atomicAdd(dst + 1, a0.y + a1.y);
    atomicAdd(dst + 2, a0.z + a1.z);
    atomicAdd(dst + 3, a0.w + a1.w);
}

__global__ void __launch_bounds__(256, 8)
se_reduce_kernel(const float4* __restrict__ feats,
                 const int*    __restrict__ idx,
                 int N) {
    const int c4  = threadIdx.x & 63;   // channel float4 lane
    const int sub = threadIdx.x >> 6;   // 0..3

    // even contiguous partition of rows across blocks
    long r0 = (long)blockIdx.x * N / gridDim.x;
    long r1 = (long)(blockIdx.x + 1) * N / gridDim.x;
    if (r0 >= r1) return;

    float4 a0 = make_float4(0.f, 0.f, 0.f, 0.f);
    float4 a1 = make_float4(0.f, 0.f, 0.f, 0.f);
    int cur = __ldg(&idx[r0]);

    long cs = r0;
    while (cs < r1) {
        long ce = cs + CHUNK;
        if (ce > r1) ce = r1;
        int s_last = __ldg(&idx[ce - 1]);

        if (s_last == cur) {
            // fast path: whole chunk in this thread's current segment.
            // 2 independent in-flight loads per iteration (rows r, r+4).
            const float4* p = feats + (cs + sub) * C4 + c4;
            long r = cs + sub;
            for (; r + 4 < ce; r += 8) {
                float4 v0 = __ldcs(p);
                float4 v1 = __ldcs(p + 4 * C4);
                a0.x += v0.x; a0.y += v0.y; a0.z += v0.z; a0.w += v0.w;
                a1.x += v1.x; a1.y += v1.y; a1.z += v1.z; a1.w += v1.w;
                p += 8 * C4;
            }
            for (; r < ce; r += 4) {
                float4 v = __ldcs(p);
                a0.x += v.x; a0.y += v.y; a0.z += v.z; a0.w += v.w;
                p += 4 * C4;
            }
        } else {
            // boundary chunk: per-row segment tracking
            for (long r = cs + sub; r < ce; r += 4) {
                int s = __ldg(&idx[r]);
                float4 v = __ldcs(feats + r * C4 + c4);
                if (s != cur) {
                    flush_acc(cur, c4, a0, a1);
                    a0 = v;
                    a1 = make_float4(0.f, 0.f, 0.f, 0.f);
                    cur = s;
                } else {
                    a0.x += v.x; a0.y += v.y; a0.z += v.z; a0.w += v.w;
                }
            }
        }
        cs = ce;
    }
    flush_acc(cur, c4, a0, a1);
}

// ---------------------------------------------------------------------------
// Kernel 2: one block per segment. Binary-search bounds (sorted idx), mean,
// 256->16 GEMM (16-thread groups + shuffle reduce), ReLU, 16->256 GEMM,
// sigmoid. Afterwards, re-zeroes its g_sum slice (restores launch invariant).
// ---------------------------------------------------------------------------
__global__ void se_mlp_kernel(const int*   __restrict__ idx, int N,
                              const float* __restrict__ W1,
                              const float* __restrict__ b1,
                              const float* __restrict__ W2,
                              const float* __restrict__ b2) {
    const int s = blockIdx.x;
    const int t = threadIdx.x;
    __shared__ float sp[C];
    __shared__ float sh[16];
    __shared__ int   lb[2];

    // lower_bound(idx, s) and lower_bound(idx, s+1)
    if (t < 2) {
        int target = s + t;
        int lo = 0, hi = N;
        while (lo < hi) {
            int mid = (lo + hi) >> 1;
            if (__ldg(&idx[mid]) < target) lo = mid + 1; else hi = mid;
        }
        lb[t] = lo;
    }
    __syncthreads();

    float inv_cnt = 1.0f / fmaxf((float)(lb[1] - lb[0]), 1.0f);
    sp[t] = g_sum[s * C + t] * inv_cnt;
    g_sum[s * C + t] = 0.0f;     // consumer reset: restore zero invariant
    __syncthreads();

    // h[g] = relu(dot(sp, W1[:,g]) + b1[g]); 16 threads per output g
    {
        int g = t >> 4;       // output 0..15
        int l = t & 15;       // lane within group
        float acc = 0.0f;
        #pragma unroll
        for (int k = l; k < C; k += 16) acc += sp[k] * W1[k * 16 + g];
        #pragma unroll
        for (int off = 8; off; off >>= 1)
            acc += __shfl_down_sync(0xffffffffu, acc, off, 16);
        if (l == 0) sh[g] = fmaxf(acc + b1[g], 0.0f);
    }
    __syncthreads();

    // y[t] = sigmoid(dot(sh, W2[:,t]) + b2[t])
    float acc = b2[t];
    #pragma unroll
    for (int k = 0; k < 16; k++) acc += sh[k] * W2[k * C + t];
    ((float*)g_y4)[s * C + t] = 1.0f / (1.0f + __expf(-acc));
}

// ---------------------------------------------------------------------------
// Kernel 3: out = feats * y[batch_idx].  Flat float4 grid-stride, PLAIN
// loads/stores (R4 showed cache-streaming hints hurt this RMW stream; the
// plain version measured 298 us @ 84.9% DRAM in R3).
// ---------------------------------------------------------------------------
__global__ void se_scale_kernel(const float4* __restrict__ feats,
                                const int*    __restrict__ idx,
                                float4*       __restrict__ out,
                                long total4) {
    long stride = (long)gridDim.x * blockDim.x;
    for (long i = (long)blockIdx.x * blockDim.x + threadIdx.x;
         i < total4; i += stride) {
        int row = (int)(i >> 6);
        int c4  = (int)(i & 63);
        int s   = __ldg(&idx[row]);
        float4 v = feats[i];
        float4 g = g_y4[s * C4 + c4];
        float4 o;
        o.x = v.x * g.x; o.y = v.y * g.y; o.z = v.z * g.z; o.w = v.w * g.w;
        out[i] = o;
    }
}

// ---------------------------------------------------------------------------
extern "C" void kernel_launch(void* const* d_in, const int* in_sizes, int n_in,
                              void* d_out, int out_size) {
    const float* feats = (const float*)d_in[0];
    const int*   idx   = (const int*)  d_in[1];
    const float* W1    = (const float*)d_in[2];
    const float* b1    = (const float*)d_in[3];
    const float* W2    = (const float*)d_in[4];
    const float* b2    = (const float*)d_in[5];

    const int N = in_sizes[1];               // number of points
    const long total4 = (long)N * C4;

    se_reduce_kernel<<<RED_BLOCKS, 256>>>((const float4*)feats, idx, N);

    se_mlp_kernel<<<NUM_SEG, 256>>>(idx, N, W1, b1, W2, b2);

    se_scale_kernel<<<2368, 256>>>((const float4*)feats, idx,
                                   (float4*)d_out, total4);
}